// round 16
// baseline (speedup 1.0000x reference)
#include <cuda_runtime.h>
#include <cuda_fp16.h>

#define GRID 148
#define NTHR 512
#define Bsz 64
#define Ssz 1024
#define Tsz 300
#define Hsz 512
#define Vsz 5000
#define KQn 256

typedef unsigned long long ull;

// ---------------- device scratch ----------------
__device__ __half g_k[Bsz * Ssz * KQn];
__device__ __half g_v[Bsz * Ssz * Hsz];
// hi/lo fp16 weight copies
__device__ __half g_w1ih_h[2048 * 1024], g_w1ih_l[2048 * 1024];
__device__ __half g_w1hh_h[2048 * 512],  g_w1hh_l[2048 * 512];
__device__ __half g_w2ih_h[2048 * 512],  g_w2ih_l[2048 * 512];
__device__ __half g_w2hh_h[2048 * 512],  g_w2hh_l[2048 * 512];
__device__ __half g_wcd_h[512 * 1024],   g_wcd_l[512 * 1024];
__device__ __half g_emb_h[Vsz * 512],    g_emb_l[Vsz * 512];
__device__ float g_h1[2][Bsz * Hsz];
__device__ float g_c1[Bsz * Hsz];
__device__ float g_h2[2][Bsz * Hsz];
__device__ float g_c2[Bsz * Hsz];
__device__ float g_ctx[Bsz * Hsz];
__device__ float g_cdn[Bsz * Hsz];
__device__ float g_g1p[4 * Bsz * 2048];
__device__ float g_g2p[4 * Bsz * 2048];
__device__ float g_cdp[8 * Bsz * 512];
__device__ float g_lgp[2][Bsz * 5120];
__device__ volatile int g_flags[GRID];
__device__ volatile int g_genv;

// ---------------- shared arena ----------------
struct __align__(16) Sh {
    union {
        struct { float As[64][36]; float Bs[128][36]; } g;          // fp32 gemm
        struct { __half Ah[64][40]; __half Al[64][40];
                 __half Bh[128][40]; __half Bl[128][40]; } th;      // tensor
        struct { float h2s[512]; float qs[256]; float sc[1024];
                 float red[16]; float part[8][528]; } a;            // attention
    } u;
    int toks[64];
};

// ---------------- grid barrier ----------------
__device__ __forceinline__ void gsync(int& gs) {
    gs++;
    __syncthreads();
    if (blockIdx.x == 0) {
        if (threadIdx.x > 0 && threadIdx.x < GRID)
            while (g_flags[threadIdx.x] < gs) __nanosleep(32);
        __syncthreads();
        if (threadIdx.x == 0) { __threadfence(); g_genv = gs; }
    } else if (threadIdx.x == 0) {
        __threadfence();
        g_flags[blockIdx.x] = gs;
        while (g_genv < gs) __nanosleep(32);
    }
    __syncthreads();
    __threadfence();
}

__device__ __forceinline__ float sigf(float x) { return 1.f / (1.f + __expf(-x)); }

__device__ __forceinline__ void fma2(ull& d, ull a, ull b) {
    asm("fma.rn.f32x2 %0, %1, %2, %3;" : "=l"(d) : "l"(a), "l"(b), "l"(d));
}
__device__ __forceinline__ float pairsum(ull x) {
    float lo, hi;
    asm("mov.b64 {%0, %1}, %2;" : "=f"(lo), "=f"(hi) : "l"(x));
    return lo + hi;
}
__device__ __forceinline__ float2 h2f(unsigned p) {
    __half2 h = *reinterpret_cast<__half2*>(&p);
    return __half22float2(h);
}
#define MMA16816(ACC, A0, A1, A2, A3, B0, B1)                                \
    asm volatile(                                                            \
        "mma.sync.aligned.m16n8k16.row.col.f32.f16.f16.f32 "                 \
        "{%0,%1,%2,%3}, {%4,%5,%6,%7}, {%8,%9}, {%0,%1,%2,%3};"              \
        : "+f"(ACC[0]), "+f"(ACC[1]), "+f"(ACC[2]), "+f"(ACC[3])             \
        : "r"(A0), "r"(A1), "r"(A2), "r"(A3), "r"(B0), "r"(B1))

// ---------------- hi/lo split tensor GEMM: 64M x 128N ----------------------
// out[m][n] = sum_k A[m][k]*B[n][k]; A fp32 split to hi/lo fp16 on the fly;
// B pre-split hi/lo fp16. 3 HMMA per fragment (hh + hl + lh), fp32 accum.
// AM 1: A = [emb[tok]|A1|A2] each 512. AM 2: A = [A0(512)|A1(512..)].
// B row n: k<segB -> B0 (len L0) else B1 (len L1).
template <int AM>
__device__ __forceinline__ void gemmT(
    const float* __restrict__ A0, const float* __restrict__ A1,
    const float* __restrict__ A2,
    const __half* __restrict__ B0h, const __half* __restrict__ B0l,
    long L0, int segB,
    const __half* __restrict__ B1h, const __half* __restrict__ B1l, long L1,
    int nbase, int Nmax, int kbeg, int kend,
    float* __restrict__ outp, long OS,
    const int* __restrict__ yy, int t, Sh& sh)
{
    const int tid = threadIdx.x;
    const int lane = tid & 31, w = tid >> 5;
    const int mw = (w & 3) * 16;
    const int nw = (w >> 2) * 32;
    const int gr = lane >> 2;
    const int kc2 = (lane & 3) * 2;
    const int arow = tid >> 3;
    const int acol = (tid & 7) * 4;
    const int brow = tid >> 2;
    const int bcol = (tid & 3) * 8;

    if (AM == 1) {
        if (tid < 64) sh.toks[tid] = (t == 0) ? 0 : yy[tid * Tsz + (t - 1)];
        __syncthreads();
    }

    float acc[4][4];
#pragma unroll
    for (int j = 0; j < 4; j++)
#pragma unroll
        for (int i = 0; i < 4; i++) acc[j][i] = 0.f;

    for (int kb = kbeg; kb < kend; kb += 32) {
        // ---- A fill: fp32 -> hi/lo fp16 ----
        {
            int k = kb + acol;
            const float* rp;
            if (AM == 1) rp = (k < 512)  ? A0 + (long)sh.toks[arow] * 512 + k
                           : (k < 1024) ? A1 + arow * 512 + (k - 512)
                                        : A2 + arow * 512 + (k - 1024);
            else         rp = (k < 512)  ? A0 + arow * 512 + k
                                         : A1 + arow * 512 + (k - 512);
            float4 v = *(const float4*)rp;
            __half2 h0 = __floats2half2_rn(v.x, v.y);
            __half2 h1 = __floats2half2_rn(v.z, v.w);
            float2 f0 = __half22float2(h0);
            float2 f1 = __half22float2(h1);
            __half2 l0 = __floats2half2_rn(v.x - f0.x, v.y - f0.y);
            __half2 l1 = __floats2half2_rn(v.z - f1.x, v.w - f1.y);
            *(uint2*)&sh.u.th.Ah[arow][acol] =
                make_uint2(*(unsigned*)&h0, *(unsigned*)&h1);
            *(uint2*)&sh.u.th.Al[arow][acol] =
                make_uint2(*(unsigned*)&l0, *(unsigned*)&l1);
        }
        // ---- B fill: hi/lo fp16 copies ----
        {
            int ng = nbase + brow;
            int k = kb + bcol;
            uint4 vh = make_uint4(0, 0, 0, 0), vl = make_uint4(0, 0, 0, 0);
            if (ng < Nmax) {
                if (k < segB) {
                    long off = (long)ng * L0 + k;
                    vh = *(const uint4*)(B0h + off);
                    vl = *(const uint4*)(B0l + off);
                } else {
                    long off = (long)ng * L1 + (k - segB);
                    vh = *(const uint4*)(B1h + off);
                    vl = *(const uint4*)(B1l + off);
                }
            }
            *(uint4*)&sh.u.th.Bh[brow][bcol] = vh;
            *(uint4*)&sh.u.th.Bl[brow][bcol] = vl;
        }
        __syncthreads();
#pragma unroll
        for (int h = 0; h < 2; h++) {
            int k0 = h * 16;
            unsigned a0 = *(const unsigned*)&sh.u.th.Ah[mw + gr][k0 + kc2];
            unsigned a1 = *(const unsigned*)&sh.u.th.Ah[mw + 8 + gr][k0 + kc2];
            unsigned a2 = *(const unsigned*)&sh.u.th.Ah[mw + gr][k0 + kc2 + 8];
            unsigned a3 = *(const unsigned*)&sh.u.th.Ah[mw + 8 + gr][k0 + kc2 + 8];
            unsigned la0 = *(const unsigned*)&sh.u.th.Al[mw + gr][k0 + kc2];
            unsigned la1 = *(const unsigned*)&sh.u.th.Al[mw + 8 + gr][k0 + kc2];
            unsigned la2 = *(const unsigned*)&sh.u.th.Al[mw + gr][k0 + kc2 + 8];
            unsigned la3 = *(const unsigned*)&sh.u.th.Al[mw + 8 + gr][k0 + kc2 + 8];
#pragma unroll
            for (int j = 0; j < 4; j++) {
                int n = nw + j * 8 + gr;
                unsigned b0 = *(const unsigned*)&sh.u.th.Bh[n][k0 + kc2];
                unsigned b1 = *(const unsigned*)&sh.u.th.Bh[n][k0 + kc2 + 8];
                unsigned lb0 = *(const unsigned*)&sh.u.th.Bl[n][k0 + kc2];
                unsigned lb1 = *(const unsigned*)&sh.u.th.Bl[n][k0 + kc2 + 8];
                MMA16816(acc[j], a0, a1, a2, a3, b0, b1);    // hi*hi
                MMA16816(acc[j], a0, a1, a2, a3, lb0, lb1);  // hi*lo
                MMA16816(acc[j], la0, la1, la2, la3, b0, b1);// lo*hi
            }
        }
        __syncthreads();
    }

#pragma unroll
    for (int j = 0; j < 4; j++) {
        int nn = nbase + nw + j * 8 + kc2;
        if (nn < Nmax) {
            long m0 = mw + gr, m1 = mw + 8 + gr;
            *(float2*)&outp[m0 * OS + nn] = make_float2(acc[j][0], acc[j][1]);
            *(float2*)&outp[m1 * OS + nn] = make_float2(acc[j][2], acc[j][3]);
        }
    }
}

// ---------------- fp32 f32x2 GEMM (kv projection only) ---------------------
template <int AM, int OB>
__device__ __forceinline__ void gemm2(
    const float* __restrict__ A0, long arow,
    const float* __restrict__ B0, long L0,
    int nbase, int kbeg, int kend,
    void* __restrict__ outp, long OS, const float* __restrict__ bias, Sh& sh)
{
    const int tid = threadIdx.x;
    const int nt = tid & 31;
    const int mt = tid >> 5;
    const int ar = tid >> 3;
    const int kq4 = (tid & 7) * 4;

    ull acc[4][4];
#pragma unroll
    for (int i = 0; i < 4; i++)
#pragma unroll
        for (int j = 0; j < 4; j++) acc[i][j] = 0ULL;

    float4 pa, pb0, pb1;
    auto loadA = [&](int kb, float4& d) {
        d = *(const float4*)(A0 + (long)ar * arow + kb + kq4);
    };
    auto loadB = [&](int kb, int n, float4& d) {
        d = *(const float4*)(B0 + (long)(nbase + n) * L0 + kb + kq4);
    };

    loadA(kbeg, pa);
    loadB(kbeg, ar, pb0);
    loadB(kbeg, ar + 64, pb1);

    for (int kb = kbeg; kb < kend; kb += 32) {
        __syncthreads();
        *(float4*)&sh.u.g.As[ar][kq4]      = pa;
        *(float4*)&sh.u.g.Bs[ar][kq4]      = pb0;
        *(float4*)&sh.u.g.Bs[ar + 64][kq4] = pb1;
        __syncthreads();
        if (kb + 32 < kend) {
            loadA(kb + 32, pa);
            loadB(kb + 32, ar, pb0);
            loadB(kb + 32, ar + 64, pb1);
        }
#pragma unroll
        for (int kq = 0; kq < 8; kq++) {
            ull a0[4], a1[4], b0[4], b1[4];
#pragma unroll
            for (int j = 0; j < 4; j++) {
                ulonglong2 tb = *(const ulonglong2*)&sh.u.g.Bs[nt + 32 * j][4 * kq];
                b0[j] = tb.x; b1[j] = tb.y;
            }
#pragma unroll
            for (int i = 0; i < 4; i++) {
                ulonglong2 ta = *(const ulonglong2*)&sh.u.g.As[mt * 4 + i][4 * kq];
                a0[i] = ta.x; a1[i] = ta.y;
            }
#pragma unroll
            for (int i = 0; i < 4; i++)
#pragma unroll
                for (int j = 0; j < 4; j++) {
                    fma2(acc[i][j], a0[i], b0[j]);
                    fma2(acc[i][j], a1[i], b1[j]);
                }
        }
    }
    __syncthreads();

#pragma unroll
    for (int i = 0; i < 4; i++) {
        long m = mt * 4 + i;
#pragma unroll
        for (int j = 0; j < 4; j++) {
            int n = nbase + nt + 32 * j;
            float s = pairsum(acc[i][j]) + bias[n];
            if (OB) ((__half*)outp)[m * OS + n] = __float2half(s);
            else    ((float*)outp)[m * OS + n] = s;
        }
    }
}

// ---------------- persistent mega-kernel ----------------
__global__ void __launch_bounds__(NTHR, 1)
mega(const float* __restrict__ enc, const int* __restrict__ y,
     const float* __restrict__ emb,
     const float* __restrict__ Wq, const float* __restrict__ bq,
     const float* __restrict__ Wk, const float* __restrict__ bk,
     const float* __restrict__ Wv, const float* __restrict__ bv,
     const float* __restrict__ Wih1, const float* __restrict__ bih1,
     const float* __restrict__ Whh1, const float* __restrict__ bhh1,
     const float* __restrict__ Wih2, const float* __restrict__ bih2,
     const float* __restrict__ Whh2, const float* __restrict__ bhh2,
     const float* __restrict__ Wcdn, const float* __restrict__ bcdn,
     const float* __restrict__ bcls, float* __restrict__ out)
{
    __shared__ Sh sh;
    const int tid = threadIdx.x;
    const int bx = blockIdx.x;
    int gs = g_genv;

    // ---- init: zero state + hi/lo weight conversion ----
    {
        int gid = bx * NTHR + tid;
        const int STR = GRID * NTHR;
        for (int i = gid; i < 5 * Bsz * Hsz; i += STR) {
            int a = i >> 15, j = i & 32767;
            float* p = a == 0 ? g_h1[0] : a == 1 ? g_c1 : a == 2 ? g_h2[0]
                     : a == 3 ? g_c2 : g_ctx;
            p[j] = 0.f;
        }
        auto cvt = [&](const float* src, __half* dh, __half* dl, int n) {
            for (int i = gid; i < n; i += STR) {
                float v = src[i];
                __half h = __float2half(v);
                dh[i] = h;
                dl[i] = __float2half(v - __half2float(h));
            }
        };
        cvt(Wih1, g_w1ih_h, g_w1ih_l, 2048 * 1024);
        cvt(Whh1, g_w1hh_h, g_w1hh_l, 2048 * 512);
        cvt(Wih2, g_w2ih_h, g_w2ih_l, 2048 * 512);
        cvt(Whh2, g_w2hh_h, g_w2hh_l, 2048 * 512);
        cvt(Wcdn, g_wcd_h,  g_wcd_l,  512 * 1024);
        cvt(emb,  g_emb_h,  g_emb_l,  Vsz * 512);
    }
    // ---- kv projection (fp32 gemm, fp16 out) ----
    for (int j = bx; j < 6144; j += GRID) {
        if (j < 2048) {
            int mt_ = j >> 1, nt_ = j & 1;
            gemm2<0, 1>(enc + (long)mt_ * 64 * 512, 512, Wk, 512,
                        nt_ * 128, 0, 512,
                        g_k + (long)mt_ * 64 * KQn, KQn, bk, sh);
        } else {
            int v = j - 2048;
            int mt_ = v >> 2, nt_ = v & 3;
            gemm2<0, 1>(enc + (long)mt_ * 64 * 512, 512, Wv, 512,
                        nt_ * 128, 0, 512,
                        g_v + (long)mt_ * 64 * Hsz, Hsz, bv, sh);
        }
    }
    gsync(gs);

    for (int t = 0; t < Tsz; t++) {
        const float* h1o = g_h1[t & 1];
        float*       h1n = g_h1[(t + 1) & 1];
        const float* h2o = g_h2[t & 1];
        float*       h2n = g_h2[(t + 1) & 1];

        // ---- P1: LSTM1-T (0-63: 16nt x 4sk) || cdn-T(t-1) (64-95: 4nt x 8sk) ----
        if (bx < 64) {
            int ntile = bx >> 2, ks = bx & 3;
            gemmT<1>(emb, g_ctx, h1o,
                     g_w1ih_h, g_w1ih_l, 1024, 1024,
                     g_w1hh_h, g_w1hh_l, 512,
                     ntile * 128, 1 << 30, ks * 384, ks * 384 + 384,
                     g_g1p + (long)ks * 131072, 2048, y, t, sh);
        } else if (t > 0 && bx < 96) {
            int u = bx - 64, ntile = u >> 3, ks = u & 7;
            gemmT<2>(h2o, g_ctx, nullptr,
                     g_wcd_h, g_wcd_l, 1024, 1 << 30,
                     nullptr, nullptr, 0,
                     ntile * 128, 1 << 30, ks * 128, ks * 128 + 128,
                     g_cdp + (long)ks * 32768, 512, nullptr, 0, sh);
        }
        gsync(gs);

        // ---- P2: cell1 + cdn-red(t-1) + logits-red(t-2) ----
        {
            int gid = bx * NTHR + tid;
            if (gid < 32768) {
                int b = gid >> 9, u = gid & 511;
                float gt[4];
#pragma unroll
                for (int g = 0; g < 4; g++) {
                    int n = g * 512 + u;
                    float s = bih1[n] + bhh1[n];
#pragma unroll
                    for (int ks = 0; ks < 4; ks++)
                        s += g_g1p[ks * 131072 + b * 2048 + n];
                    gt[g] = s;
                }
                float cn = sigf(gt[1]) * g_c1[gid] + sigf(gt[0]) * tanhf(gt[2]);
                g_c1[gid] = cn;
                h1n[gid] = sigf(gt[3]) * tanhf(cn);
            } else if (t > 0 && gid < 65536) {
                int idx = gid - 32768;
                float s = bcdn[idx & 511];
#pragma unroll
                for (int ks = 0; ks < 8; ks++) s += g_cdp[ks * 32768 + idx];
                g_cdn[idx] = fmaxf(s, 0.f);
            }
            if (t > 1) {
                for (int e = gid; e < Bsz * Vsz; e += GRID * NTHR) {
                    int m = e / Vsz, n = e - m * Vsz;
                    out[((long)m * Tsz + (t - 2)) * Vsz + n] =
                        g_lgp[0][m * 5120 + n] + g_lgp[1][m * 5120 + n] + bcls[n];
                }
            }
            gsync(gs);
        }

        // ---- P3: LSTM2-T (0-63: 16nt x 4sk, k=256) ----
        if (bx < 64) {
            int ntile = bx >> 2, ks = bx & 3;
            gemmT<2>(h1n, h2o, nullptr,
                     g_w2ih_h, g_w2ih_l, 512, 512,
                     g_w2hh_h, g_w2hh_l, 512,
                     ntile * 128, 1 << 30, ks * 256, ks * 256 + 256,
                     g_g2p + (long)ks * 131072, 2048, nullptr, 0, sh);
        }
        gsync(gs);

        // ---- P4: attention (0-63) || logits-T(t-1) (64-143: 40nt x 2sk) ----
        if (bx < 64) {
            int b = bx, lane = tid & 31, w = tid >> 5;
            // cell2
            {
                int u = tid;
                float gt[4];
#pragma unroll
                for (int g = 0; g < 4; g++) {
                    int n = g * 512 + u;
                    float s = bih2[n] + bhh2[n];
#pragma unroll
                    for (int ks = 0; ks < 4; ks++)
                        s += g_g2p[ks * 131072 + b * 2048 + n];
                    gt[g] = s;
                }
                float cn = sigf(gt[1]) * g_c2[b * 512 + u] + sigf(gt[0]) * tanhf(gt[2]);
                float h = sigf(gt[3]) * tanhf(cn);
                g_c2[b * 512 + u] = cn;
                h2n[b * 512 + u] = h;
                sh.u.a.h2s[u] = h;
            }
            __syncthreads();
            // q projection
            {
                const float4* h24 = (const float4*)sh.u.a.h2s;
                float4 hv0 = h24[lane], hv1 = h24[32 + lane],
                       hv2 = h24[64 + lane], hv3 = h24[96 + lane];
#pragma unroll 2
                for (int jj = 0; jj < 16; jj++) {
                    int j = w * 16 + jj;
                    const float4* wr = (const float4*)(Wq + (long)j * 512);
                    float4 w0 = wr[lane], w1 = wr[32 + lane],
                           w2 = wr[64 + lane], w3 = wr[96 + lane];
                    float s = hv0.x * w0.x + hv0.y * w0.y + hv0.z * w0.z + hv0.w * w0.w
                            + hv1.x * w1.x + hv1.y * w1.y + hv1.z * w1.z + hv1.w * w1.w
                            + hv2.x * w2.x + hv2.y * w2.y + hv2.z * w2.z + hv2.w * w2.w
                            + hv3.x * w3.x + hv3.y * w3.y + hv3.z * w3.z + hv3.w * w3.w;
#pragma unroll
                    for (int o = 16; o; o >>= 1) s += __shfl_xor_sync(~0u, s, o);
                    if (lane == 0) sh.u.a.qs[j] = (s + bq[j]) * 0.0625f;
                }
            }
            __syncthreads();
            // scores
            {
                const float4* q4 = (const float4*)sh.u.a.qs;
                float4 qA = q4[2 * lane], qB = q4[2 * lane + 1];
                int rbase = w * 64;
#pragma unroll 4
                for (int i = 0; i < 64; i++) {
                    int row = rbase + i;
                    uint4 kv = *(const uint4*)(g_k + ((long)b * 1024 + row) * 256 + lane * 8);
                    float2 f0 = h2f(kv.x), f1 = h2f(kv.y),
                           f2 = h2f(kv.z), f3 = h2f(kv.w);
                    float a = qA.x * f0.x + qA.y * f0.y + qA.z * f1.x + qA.w * f1.y
                            + qB.x * f2.x + qB.y * f2.y + qB.z * f3.x + qB.w * f3.y;
#pragma unroll
                    for (int o = 16; o; o >>= 1) a += __shfl_xor_sync(~0u, a, o);
                    if (lane == 0) sh.u.a.sc[row] = a;
                }
            }
            __syncthreads();
            // softmax
            float inv;
            {
                float* sc = sh.u.a.sc;
                float* red = sh.u.a.red;
                float mx = fmaxf(sc[tid], sc[tid + 512]);
#pragma unroll
                for (int o = 16; o; o >>= 1) mx = fmaxf(mx, __shfl_xor_sync(~0u, mx, o));
                if (lane == 0) red[w] = mx;
                __syncthreads();
                mx = red[0];
#pragma unroll
                for (int i = 1; i < 16; i++) mx = fmaxf(mx, red[i]);
                __syncthreads();
                float e0 = __expf(sc[tid] - mx);
                float e1 = __expf(sc[tid + 512] - mx);
                sc[tid] = e0; sc[tid + 512] = e1;
                float ls = e0 + e1;
#pragma unroll
                for (int o = 16; o; o >>= 1) ls += __shfl_xor_sync(~0u, ls, o);
                if (lane == 0) red[w] = ls;
                __syncthreads();
                float tot = 0.f;
#pragma unroll
                for (int i = 0; i < 16; i++) tot += red[i];
                inv = 1.f / tot;
            }
            // context
            {
                const float* sc = sh.u.a.sc;
                int cg = tid & 63, sg = tid >> 6;
                const __half* vbase =
                    g_v + (long)b * (Ssz * Hsz) + (long)sg * 128 * 512 + cg * 8;
                float a0 = 0.f, a1 = 0.f, a2 = 0.f, a3 = 0.f;
                float a4 = 0.f, a5 = 0.f, a6 = 0.f, a7 = 0.f;
                const float* scp = sc + sg * 128;
#pragma unroll 8
                for (int s2 = 0; s2 < 128; s2++) {
                    uint4 vv = *(const uint4*)(vbase + (long)s2 * 512);
                    float wsc = scp[s2];
                    float2 f0 = h2f(vv.x), f1 = h2f(vv.y),
                           f2 = h2f(vv.z), f3 = h2f(vv.w);
                    a0 += wsc * f0.x; a1 += wsc * f0.y;
                    a2 += wsc * f1.x; a3 += wsc * f1.y;
                    a4 += wsc * f2.x; a5 += wsc * f2.y;
                    a6 += wsc * f3.x; a7 += wsc * f3.y;
                }
                float* pp = &sh.u.a.part[sg][cg * 8];
                *(float4*)pp       = make_float4(a0, a1, a2, a3);
                *(float4*)(pp + 4) = make_float4(a4, a5, a6, a7);
                __syncthreads();
                float s = 0.f;
#pragma unroll
                for (int g = 0; g < 8; g++) s += sh.u.a.part[g][tid];
                g_ctx[b * 512 + tid] = s * inv;
            }
        } else if (t > 0 && bx < 144) {
            int u = bx - 64, tile = u >> 1, kh = u & 1;
            gemmT<2>(g_cdn, nullptr, nullptr,
                     g_emb_h, g_emb_l, 512, 1 << 30,
                     nullptr, nullptr, 0,
                     tile * 128, Vsz, kh * 256, kh * 256 + 256,
                     g_lgp[kh], 5120, nullptr, 0, sh);
        }
        gsync(gs);
    }

    // ---- epilogue ----
    {
        const float* h2last = g_h2[Tsz & 1];
        // E1: cdn-T(Tsz-1) (0-31) || logits-red(Tsz-2) (32-147)
        if (bx < 32) {
            int ntile = bx >> 3, ks = bx & 7;
            gemmT<2>(h2last, g_ctx, nullptr,
                     g_wcd_h, g_wcd_l, 1024, 1 << 30,
                     nullptr, nullptr, 0,
                     ntile * 128, 1 << 30, ks * 128, ks * 128 + 128,
                     g_cdp + (long)ks * 32768, 512, nullptr, 0, sh);
        } else {
            int gid = (bx - 32) * NTHR + tid;
            for (int e = gid; e < Bsz * Vsz; e += 116 * NTHR) {
                int m = e / Vsz, n = e - m * Vsz;
                out[((long)m * Tsz + (Tsz - 2)) * Vsz + n] =
                    g_lgp[0][m * 5120 + n] + g_lgp[1][m * 5120 + n] + bcls[n];
            }
        }
        gsync(gs);
        // E2: cdn-reduce(Tsz-1)
        {
            int gid = bx * NTHR + tid;
            if (gid < 32768) {
                float s = bcdn[gid & 511];
#pragma unroll
                for (int ks = 0; ks < 8; ks++) s += g_cdp[ks * 32768 + gid];
                g_cdn[gid] = fmaxf(s, 0.f);
            }
        }
        gsync(gs);
        // E3: logits-T(Tsz-1) on 80 blocks
        if (bx < 80) {
            int tile = bx >> 1, kh = bx & 1;
            gemmT<2>(g_cdn, nullptr, nullptr,
                     g_emb_h, g_emb_l, 512, 1 << 30,
                     nullptr, nullptr, 0,
                     tile * 128, Vsz, kh * 256, kh * 256 + 256,
                     g_lgp[kh], 5120, nullptr, 0, sh);
        }
        gsync(gs);
        // E4: logits-red(Tsz-1)
        {
            int gid = bx * NTHR + tid;
            for (int e = gid; e < Bsz * Vsz; e += GRID * NTHR) {
                int m = e / Vsz, n = e - m * Vsz;
                out[((long)m * Tsz + (Tsz - 1)) * Vsz + n] =
                    g_lgp[0][m * 5120 + n] + g_lgp[1][m * 5120 + n] + bcls[n];
            }
        }
    }
}

extern "C" void kernel_launch(void* const* d_in, const int* in_sizes, int n_in,
                              void* d_out, int out_size) {
    mega<<<GRID, NTHR>>>(
        (const float*)d_in[0],  (const int*)d_in[1],   (const float*)d_in[2],
        (const float*)d_in[3],  (const float*)d_in[4],
        (const float*)d_in[5],  (const float*)d_in[6],
        (const float*)d_in[7],  (const float*)d_in[8],
        (const float*)d_in[9],  (const float*)d_in[10],
        (const float*)d_in[11], (const float*)d_in[12],
        (const float*)d_in[13], (const float*)d_in[14],
        (const float*)d_in[15], (const float*)d_in[16],
        (const float*)d_in[17], (const float*)d_in[18],
        (const float*)d_in[19], (float*)d_out);
}

// round 17
// speedup vs baseline: 1.1609x; 1.1609x over previous
#include <cuda_runtime.h>
#include <cuda_fp16.h>

#define GRID 148
#define NTHR 512
#define Bsz 64
#define Ssz 1024
#define Tsz 300
#define Hsz 512
#define Vsz 5000
#define KQn 256

typedef unsigned long long ull;

// ---------------- device scratch ----------------
__device__ __half g_k[Bsz * Ssz * KQn];
__device__ __half g_v[Bsz * Ssz * Hsz];
// hi/lo fp16 weight copies
__device__ __half g_w1ih_h[2048 * 1024], g_w1ih_l[2048 * 1024];
__device__ __half g_w1hh_h[2048 * 512],  g_w1hh_l[2048 * 512];
__device__ __half g_w2ih_h[2048 * 512],  g_w2ih_l[2048 * 512];
__device__ __half g_w2hh_h[2048 * 512],  g_w2hh_l[2048 * 512];
__device__ __half g_wcd_h[512 * 1024],   g_wcd_l[512 * 1024];
__device__ __half g_emb_h[Vsz * 512],    g_emb_l[Vsz * 512];
__device__ float g_h1[2][Bsz * Hsz];
__device__ float g_c1[Bsz * Hsz];
__device__ float g_h2[2][Bsz * Hsz];
__device__ float g_c2[Bsz * Hsz];
__device__ float g_ctx[Bsz * Hsz];
__device__ float g_cdn[Bsz * Hsz];
__device__ float g_g1p[8 * Bsz * 2048];
__device__ float g_g2p[9 * Bsz * 2048];
__device__ float g_cdp[5 * Bsz * 512];
__device__ float g_lgp[2][Bsz * 5120];
__device__ volatile int g_flags[GRID];
__device__ volatile int g_genv;

// ---------------- shared arena ----------------
struct __align__(16) Sh {
    union {
        struct { float As[64][36]; float Bs[128][36]; } g;          // fp32 gemm
        struct { __half Ah[64][40]; __half Al[64][40];
                 __half Bh[128][40]; __half Bl[128][40]; } th;      // tensor
        struct { float h2s[512]; float qs[256]; float sc[1024];
                 float red[16]; float part[8][528]; } a;            // attention
    } u;
    int toks[64];
};

// ---------------- grid barrier ----------------
__device__ __forceinline__ void gsync(int& gs) {
    gs++;
    __syncthreads();
    if (blockIdx.x == 0) {
        if (threadIdx.x > 0 && threadIdx.x < GRID)
            while (g_flags[threadIdx.x] < gs) __nanosleep(32);
        __syncthreads();
        if (threadIdx.x == 0) { __threadfence(); g_genv = gs; }
    } else if (threadIdx.x == 0) {
        __threadfence();
        g_flags[blockIdx.x] = gs;
        while (g_genv < gs) __nanosleep(32);
    }
    __syncthreads();
    __threadfence();
}

__device__ __forceinline__ float sigf(float x) { return 1.f / (1.f + __expf(-x)); }

__device__ __forceinline__ void fma2(ull& d, ull a, ull b) {
    asm("fma.rn.f32x2 %0, %1, %2, %3;" : "=l"(d) : "l"(a), "l"(b), "l"(d));
}
__device__ __forceinline__ float pairsum(ull x) {
    float lo, hi;
    asm("mov.b64 {%0, %1}, %2;" : "=f"(lo), "=f"(hi) : "l"(x));
    return lo + hi;
}
__device__ __forceinline__ float2 h2f(unsigned p) {
    __half2 h = *reinterpret_cast<__half2*>(&p);
    return __half22float2(h);
}
#define MMA16816(ACC, A0, A1, A2, A3, B0, B1)                                \
    asm volatile(                                                            \
        "mma.sync.aligned.m16n8k16.row.col.f32.f16.f16.f32 "                 \
        "{%0,%1,%2,%3}, {%4,%5,%6,%7}, {%8,%9}, {%0,%1,%2,%3};"              \
        : "+f"(ACC[0]), "+f"(ACC[1]), "+f"(ACC[2]), "+f"(ACC[3])             \
        : "r"(A0), "r"(A1), "r"(A2), "r"(A3), "r"(B0), "r"(B1))

// ---------------- hi/lo split tensor GEMM: 64M x 128N ----------------------
// out[m][n] = sum_k A[m][k]*B[n][k]; A fp32 split hi/lo on the fly;
// B pre-split hi/lo fp16. 3 HMMA (hh + hl + lh), fp32 accum.
// AM 1: A = [emb[tok]|A1|A2] each 512. AM 2: A = [A0(512)|A1(512..)].
template <int AM>
__device__ __forceinline__ void gemmT(
    const float* __restrict__ A0, const float* __restrict__ A1,
    const float* __restrict__ A2,
    const __half* __restrict__ B0h, const __half* __restrict__ B0l,
    long L0, int segB,
    const __half* __restrict__ B1h, const __half* __restrict__ B1l, long L1,
    int nbase, int Nmax, int kbeg, int kend,
    float* __restrict__ outp, long OS,
    const int* __restrict__ yy, int t, Sh& sh)
{
    const int tid = threadIdx.x;
    const int lane = tid & 31, w = tid >> 5;
    const int mw = (w & 3) * 16;
    const int nw = (w >> 2) * 32;
    const int gr = lane >> 2;
    const int kc2 = (lane & 3) * 2;
    const int arow = tid >> 3;
    const int acol = (tid & 7) * 4;
    const int brow = tid >> 2;
    const int bcol = (tid & 3) * 8;

    if (AM == 1) {
        if (tid < 64) sh.toks[tid] = (t == 0) ? 0 : yy[tid * Tsz + (t - 1)];
        __syncthreads();
    }

    float acc[4][4];
#pragma unroll
    for (int j = 0; j < 4; j++)
#pragma unroll
        for (int i = 0; i < 4; i++) acc[j][i] = 0.f;

    for (int kb = kbeg; kb < kend; kb += 32) {
        // ---- A fill: fp32 -> hi/lo fp16 ----
        {
            int k = kb + acol;
            const float* rp;
            if (AM == 1) rp = (k < 512)  ? A0 + (long)sh.toks[arow] * 512 + k
                           : (k < 1024) ? A1 + arow * 512 + (k - 512)
                                        : A2 + arow * 512 + (k - 1024);
            else         rp = (k < 512)  ? A0 + arow * 512 + k
                                         : A1 + arow * 512 + (k - 512);
            float4 v = *(const float4*)rp;
            __half2 h0 = __floats2half2_rn(v.x, v.y);
            __half2 h1 = __floats2half2_rn(v.z, v.w);
            float2 f0 = __half22float2(h0);
            float2 f1 = __half22float2(h1);
            __half2 l0 = __floats2half2_rn(v.x - f0.x, v.y - f0.y);
            __half2 l1 = __floats2half2_rn(v.z - f1.x, v.w - f1.y);
            *(uint2*)&sh.u.th.Ah[arow][acol] =
                make_uint2(*(unsigned*)&h0, *(unsigned*)&h1);
            *(uint2*)&sh.u.th.Al[arow][acol] =
                make_uint2(*(unsigned*)&l0, *(unsigned*)&l1);
        }
        // ---- B fill: hi/lo fp16 copies ----
        {
            int ng = nbase + brow;
            int k = kb + bcol;
            uint4 vh = make_uint4(0, 0, 0, 0), vl = make_uint4(0, 0, 0, 0);
            if (ng < Nmax) {
                if (k < segB) {
                    long off = (long)ng * L0 + k;
                    vh = *(const uint4*)(B0h + off);
                    vl = *(const uint4*)(B0l + off);
                } else {
                    long off = (long)ng * L1 + (k - segB);
                    vh = *(const uint4*)(B1h + off);
                    vl = *(const uint4*)(B1l + off);
                }
            }
            *(uint4*)&sh.u.th.Bh[brow][bcol] = vh;
            *(uint4*)&sh.u.th.Bl[brow][bcol] = vl;
        }
        __syncthreads();
#pragma unroll
        for (int h = 0; h < 2; h++) {
            int k0 = h * 16;
            unsigned a0 = *(const unsigned*)&sh.u.th.Ah[mw + gr][k0 + kc2];
            unsigned a1 = *(const unsigned*)&sh.u.th.Ah[mw + 8 + gr][k0 + kc2];
            unsigned a2 = *(const unsigned*)&sh.u.th.Ah[mw + gr][k0 + kc2 + 8];
            unsigned a3 = *(const unsigned*)&sh.u.th.Ah[mw + 8 + gr][k0 + kc2 + 8];
            unsigned la0 = *(const unsigned*)&sh.u.th.Al[mw + gr][k0 + kc2];
            unsigned la1 = *(const unsigned*)&sh.u.th.Al[mw + 8 + gr][k0 + kc2];
            unsigned la2 = *(const unsigned*)&sh.u.th.Al[mw + gr][k0 + kc2 + 8];
            unsigned la3 = *(const unsigned*)&sh.u.th.Al[mw + 8 + gr][k0 + kc2 + 8];
#pragma unroll
            for (int j = 0; j < 4; j++) {
                int n = nw + j * 8 + gr;
                unsigned b0 = *(const unsigned*)&sh.u.th.Bh[n][k0 + kc2];
                unsigned b1 = *(const unsigned*)&sh.u.th.Bh[n][k0 + kc2 + 8];
                unsigned lb0 = *(const unsigned*)&sh.u.th.Bl[n][k0 + kc2];
                unsigned lb1 = *(const unsigned*)&sh.u.th.Bl[n][k0 + kc2 + 8];
                MMA16816(acc[j], a0, a1, a2, a3, b0, b1);
                MMA16816(acc[j], a0, a1, a2, a3, lb0, lb1);
                MMA16816(acc[j], la0, la1, la2, la3, b0, b1);
            }
        }
        __syncthreads();
    }

#pragma unroll
    for (int j = 0; j < 4; j++) {
        int nn = nbase + nw + j * 8 + kc2;
        if (nn < Nmax) {
            long m0 = mw + gr, m1 = mw + 8 + gr;
            *(float2*)&outp[m0 * OS + nn] = make_float2(acc[j][0], acc[j][1]);
            *(float2*)&outp[m1 * OS + nn] = make_float2(acc[j][2], acc[j][3]);
        }
    }
}

// ---------------- fp32 f32x2 GEMM (kv projection only) ---------------------
template <int AM, int OB>
__device__ __forceinline__ void gemm2(
    const float* __restrict__ A0, long arow,
    const float* __restrict__ B0, long L0,
    int nbase, int kbeg, int kend,
    void* __restrict__ outp, long OS, const float* __restrict__ bias, Sh& sh)
{
    const int tid = threadIdx.x;
    const int nt = tid & 31;
    const int mt = tid >> 5;
    const int ar = tid >> 3;
    const int kq4 = (tid & 7) * 4;

    ull acc[4][4];
#pragma unroll
    for (int i = 0; i < 4; i++)
#pragma unroll
        for (int j = 0; j < 4; j++) acc[i][j] = 0ULL;

    float4 pa, pb0, pb1;
    auto loadA = [&](int kb, float4& d) {
        d = *(const float4*)(A0 + (long)ar * arow + kb + kq4);
    };
    auto loadB = [&](int kb, int n, float4& d) {
        d = *(const float4*)(B0 + (long)(nbase + n) * L0 + kb + kq4);
    };

    loadA(kbeg, pa);
    loadB(kbeg, ar, pb0);
    loadB(kbeg, ar + 64, pb1);

    for (int kb = kbeg; kb < kend; kb += 32) {
        __syncthreads();
        *(float4*)&sh.u.g.As[ar][kq4]      = pa;
        *(float4*)&sh.u.g.Bs[ar][kq4]      = pb0;
        *(float4*)&sh.u.g.Bs[ar + 64][kq4] = pb1;
        __syncthreads();
        if (kb + 32 < kend) {
            loadA(kb + 32, pa);
            loadB(kb + 32, ar, pb0);
            loadB(kb + 32, ar + 64, pb1);
        }
#pragma unroll
        for (int kq = 0; kq < 8; kq++) {
            ull a0[4], a1[4], b0[4], b1[4];
#pragma unroll
            for (int j = 0; j < 4; j++) {
                ulonglong2 tb = *(const ulonglong2*)&sh.u.g.Bs[nt + 32 * j][4 * kq];
                b0[j] = tb.x; b1[j] = tb.y;
            }
#pragma unroll
            for (int i = 0; i < 4; i++) {
                ulonglong2 ta = *(const ulonglong2*)&sh.u.g.As[mt * 4 + i][4 * kq];
                a0[i] = ta.x; a1[i] = ta.y;
            }
#pragma unroll
            for (int i = 0; i < 4; i++)
#pragma unroll
                for (int j = 0; j < 4; j++) {
                    fma2(acc[i][j], a0[i], b0[j]);
                    fma2(acc[i][j], a1[i], b1[j]);
                }
        }
    }
    __syncthreads();

#pragma unroll
    for (int i = 0; i < 4; i++) {
        long m = mt * 4 + i;
#pragma unroll
        for (int j = 0; j < 4; j++) {
            int n = nbase + nt + 32 * j;
            float s = pairsum(acc[i][j]) + bias[n];
            if (OB) ((__half*)outp)[m * OS + n] = __float2half(s);
            else    ((float*)outp)[m * OS + n] = s;
        }
    }
}

// cdn split-K: 5 chunks {224,224,192,192,192} over k=1024
__device__ __forceinline__ void cd_geom(int ks, int& kb, int& kl) {
    kb = ks < 2 ? ks * 224 : 448 + (ks - 2) * 192;
    kl = ks < 2 ? 224 : 192;
}
// LSTM2 split-K: 9 chunks {128x5, 96x4} over k=1024
__device__ __forceinline__ void l2_geom(int ks, int& kb, int& kl) {
    if (ks < 5) { kb = ks * 128; kl = 128; }
    else        { kb = 640 + (ks - 5) * 96; kl = 96; }
}

// ---------------- persistent mega-kernel ----------------
__global__ void __launch_bounds__(NTHR, 1)
mega(const float* __restrict__ enc, const int* __restrict__ y,
     const float* __restrict__ emb,
     const float* __restrict__ Wq, const float* __restrict__ bq,
     const float* __restrict__ Wk, const float* __restrict__ bk,
     const float* __restrict__ Wv, const float* __restrict__ bv,
     const float* __restrict__ Wih1, const float* __restrict__ bih1,
     const float* __restrict__ Whh1, const float* __restrict__ bhh1,
     const float* __restrict__ Wih2, const float* __restrict__ bih2,
     const float* __restrict__ Whh2, const float* __restrict__ bhh2,
     const float* __restrict__ Wcdn, const float* __restrict__ bcdn,
     const float* __restrict__ bcls, float* __restrict__ out)
{
    __shared__ Sh sh;
    const int tid = threadIdx.x;
    const int bx = blockIdx.x;
    int gs = g_genv;

    // ---- init: zero state + hi/lo weight conversion ----
    {
        int gid = bx * NTHR + tid;
        const int STR = GRID * NTHR;
        for (int i = gid; i < 5 * Bsz * Hsz; i += STR) {
            int a = i >> 15, j = i & 32767;
            float* p = a == 0 ? g_h1[0] : a == 1 ? g_c1 : a == 2 ? g_h2[0]
                     : a == 3 ? g_c2 : g_ctx;
            p[j] = 0.f;
        }
        auto cvt = [&](const float* src, __half* dh, __half* dl, int n) {
            for (int i = gid; i < n; i += STR) {
                float v = src[i];
                __half h = __float2half(v);
                dh[i] = h;
                dl[i] = __float2half(v - __half2float(h));
            }
        };
        cvt(Wih1, g_w1ih_h, g_w1ih_l, 2048 * 1024);
        cvt(Whh1, g_w1hh_h, g_w1hh_l, 2048 * 512);
        cvt(Wih2, g_w2ih_h, g_w2ih_l, 2048 * 512);
        cvt(Whh2, g_w2hh_h, g_w2hh_l, 2048 * 512);
        cvt(Wcdn, g_wcd_h,  g_wcd_l,  512 * 1024);
        cvt(emb,  g_emb_h,  g_emb_l,  Vsz * 512);
    }
    // ---- kv projection (fp32 gemm, fp16 out) ----
    for (int j = bx; j < 6144; j += GRID) {
        if (j < 2048) {
            int mt_ = j >> 1, nt_ = j & 1;
            gemm2<0, 1>(enc + (long)mt_ * 64 * 512, 512, Wk, 512,
                        nt_ * 128, 0, 512,
                        g_k + (long)mt_ * 64 * KQn, KQn, bk, sh);
        } else {
            int v = j - 2048;
            int mt_ = v >> 2, nt_ = v & 3;
            gemm2<0, 1>(enc + (long)mt_ * 64 * 512, 512, Wv, 512,
                        nt_ * 128, 0, 512,
                        g_v + (long)mt_ * 64 * Hsz, Hsz, bv, sh);
        }
    }
    gsync(gs);

    for (int t = 0; t < Tsz; t++) {
        const float* h1o = g_h1[t & 1];
        float*       h1n = g_h1[(t + 1) & 1];
        const float* h2o = g_h2[t & 1];
        float*       h2n = g_h2[(t + 1) & 1];

        // ---- P1: LSTM1-T (0-127: 16nt x 8sk, k=192)
        //          || cdn-T(t-1) (128-147: 4nt x 5sk uneven) ----
        if (bx < 128) {
            int ntile = bx >> 3, ks = bx & 7;
            gemmT<1>(emb, g_ctx, h1o,
                     g_w1ih_h, g_w1ih_l, 1024, 1024,
                     g_w1hh_h, g_w1hh_l, 512,
                     ntile * 128, 1 << 30, ks * 192, ks * 192 + 192,
                     g_g1p + (long)ks * 131072, 2048, y, t, sh);
        } else if (t > 0) {
            int u = bx - 128, ntile = u / 5, ks = u % 5;
            int kb, kl; cd_geom(ks, kb, kl);
            gemmT<2>(h2o, g_ctx, nullptr,
                     g_wcd_h, g_wcd_l, 1024, 1 << 30,
                     nullptr, nullptr, 0,
                     ntile * 128, 1 << 30, kb, kb + kl,
                     g_cdp + (long)ks * 32768, 512, nullptr, 0, sh);
        }
        gsync(gs);

        // ---- P2: cell1 + cdn-red(t-1) + logits-red(t-2) ----
        {
            int gid = bx * NTHR + tid;
            if (gid < 32768) {
                int b = gid >> 9, u = gid & 511;
                float gt[4];
#pragma unroll
                for (int g = 0; g < 4; g++) {
                    int n = g * 512 + u;
                    float s = bih1[n] + bhh1[n];
#pragma unroll
                    for (int ks = 0; ks < 8; ks++)
                        s += g_g1p[ks * 131072 + b * 2048 + n];
                    gt[g] = s;
                }
                float cn = sigf(gt[1]) * g_c1[gid] + sigf(gt[0]) * tanhf(gt[2]);
                g_c1[gid] = cn;
                h1n[gid] = sigf(gt[3]) * tanhf(cn);
            } else if (t > 0 && gid < 65536) {
                int idx = gid - 32768;
                float s = bcdn[idx & 511];
#pragma unroll
                for (int ks = 0; ks < 5; ks++) s += g_cdp[ks * 32768 + idx];
                g_cdn[idx] = fmaxf(s, 0.f);
            }
            if (t > 1) {
                for (int e = gid; e < Bsz * Vsz; e += GRID * NTHR) {
                    int m = e / Vsz, n = e - m * Vsz;
                    out[((long)m * Tsz + (t - 2)) * Vsz + n] =
                        g_lgp[0][m * 5120 + n] + g_lgp[1][m * 5120 + n] + bcls[n];
                }
            }
            gsync(gs);
        }

        // ---- P3: LSTM2-T (0-143: 16nt x 9sk uneven) ----
        if (bx < 144) {
            int ntile = bx / 9, ks = bx % 9;
            int kb, kl; l2_geom(ks, kb, kl);
            gemmT<2>(h1n, h2o, nullptr,
                     g_w2ih_h, g_w2ih_l, 512, 512,
                     g_w2hh_h, g_w2hh_l, 512,
                     ntile * 128, 1 << 30, kb, kb + kl,
                     g_g2p + (long)ks * 131072, 2048, nullptr, 0, sh);
        }
        gsync(gs);

        // ---- P4: attention (0-63) || logits-T(t-1) (64-143: 40nt x 2sk) ----
        if (bx < 64) {
            int b = bx, lane = tid & 31, w = tid >> 5;
            // cell2 (9 partials)
            {
                int u = tid;
                float gt[4];
#pragma unroll
                for (int g = 0; g < 4; g++) {
                    int n = g * 512 + u;
                    float s = bih2[n] + bhh2[n];
#pragma unroll
                    for (int ks = 0; ks < 9; ks++)
                        s += g_g2p[ks * 131072 + b * 2048 + n];
                    gt[g] = s;
                }
                float cn = sigf(gt[1]) * g_c2[b * 512 + u] + sigf(gt[0]) * tanhf(gt[2]);
                float h = sigf(gt[3]) * tanhf(cn);
                g_c2[b * 512 + u] = cn;
                h2n[b * 512 + u] = h;
                sh.u.a.h2s[u] = h;
            }
            __syncthreads();
            // q projection
            {
                const float4* h24 = (const float4*)sh.u.a.h2s;
                float4 hv0 = h24[lane], hv1 = h24[32 + lane],
                       hv2 = h24[64 + lane], hv3 = h24[96 + lane];
#pragma unroll 2
                for (int jj = 0; jj < 16; jj++) {
                    int j = w * 16 + jj;
                    const float4* wr = (const float4*)(Wq + (long)j * 512);
                    float4 w0 = wr[lane], w1 = wr[32 + lane],
                           w2 = wr[64 + lane], w3 = wr[96 + lane];
                    float s = hv0.x * w0.x + hv0.y * w0.y + hv0.z * w0.z + hv0.w * w0.w
                            + hv1.x * w1.x + hv1.y * w1.y + hv1.z * w1.z + hv1.w * w1.w
                            + hv2.x * w2.x + hv2.y * w2.y + hv2.z * w2.z + hv2.w * w2.w
                            + hv3.x * w3.x + hv3.y * w3.y + hv3.z * w3.z + hv3.w * w3.w;
#pragma unroll
                    for (int o = 16; o; o >>= 1) s += __shfl_xor_sync(~0u, s, o);
                    if (lane == 0) sh.u.a.qs[j] = (s + bq[j]) * 0.0625f;
                }
            }
            __syncthreads();
            // scores
            {
                const float4* q4 = (const float4*)sh.u.a.qs;
                float4 qA = q4[2 * lane], qB = q4[2 * lane + 1];
                int rbase = w * 64;
#pragma unroll 4
                for (int i = 0; i < 64; i++) {
                    int row = rbase + i;
                    uint4 kv = *(const uint4*)(g_k + ((long)b * 1024 + row) * 256 + lane * 8);
                    float2 f0 = h2f(kv.x), f1 = h2f(kv.y),
                           f2 = h2f(kv.z), f3 = h2f(kv.w);
                    float a = qA.x * f0.x + qA.y * f0.y + qA.z * f1.x + qA.w * f1.y
                            + qB.x * f2.x + qB.y * f2.y + qB.z * f3.x + qB.w * f3.y;
#pragma unroll
                    for (int o = 16; o; o >>= 1) a += __shfl_xor_sync(~0u, a, o);
                    if (lane == 0) sh.u.a.sc[row] = a;
                }
            }
            __syncthreads();
            // softmax
            float inv;
            {
                float* sc = sh.u.a.sc;
                float* red = sh.u.a.red;
                float mx = fmaxf(sc[tid], sc[tid + 512]);
#pragma unroll
                for (int o = 16; o; o >>= 1) mx = fmaxf(mx, __shfl_xor_sync(~0u, mx, o));
                if (lane == 0) red[w] = mx;
                __syncthreads();
                mx = red[0];
#pragma unroll
                for (int i = 1; i < 16; i++) mx = fmaxf(mx, red[i]);
                __syncthreads();
                float e0 = __expf(sc[tid] - mx);
                float e1 = __expf(sc[tid + 512] - mx);
                sc[tid] = e0; sc[tid + 512] = e1;
                float ls = e0 + e1;
#pragma unroll
                for (int o = 16; o; o >>= 1) ls += __shfl_xor_sync(~0u, ls, o);
                if (lane == 0) red[w] = ls;
                __syncthreads();
                float tot = 0.f;
#pragma unroll
                for (int i = 0; i < 16; i++) tot += red[i];
                inv = 1.f / tot;
            }
            // context
            {
                const float* sc = sh.u.a.sc;
                int cg = tid & 63, sg = tid >> 6;
                const __half* vbase =
                    g_v + (long)b * (Ssz * Hsz) + (long)sg * 128 * 512 + cg * 8;
                float a0 = 0.f, a1 = 0.f, a2 = 0.f, a3 = 0.f;
                float a4 = 0.f, a5 = 0.f, a6 = 0.f, a7 = 0.f;
                const float* scp = sc + sg * 128;
#pragma unroll 8
                for (int s2 = 0; s2 < 128; s2++) {
                    uint4 vv = *(const uint4*)(vbase + (long)s2 * 512);
                    float wsc = scp[s2];
                    float2 f0 = h2f(vv.x), f1 = h2f(vv.y),
                           f2 = h2f(vv.z), f3 = h2f(vv.w);
                    a0 += wsc * f0.x; a1 += wsc * f0.y;
                    a2 += wsc * f1.x; a3 += wsc * f1.y;
                    a4 += wsc * f2.x; a5 += wsc * f2.y;
                    a6 += wsc * f3.x; a7 += wsc * f3.y;
                }
                float* pp = &sh.u.a.part[sg][cg * 8];
                *(float4*)pp       = make_float4(a0, a1, a2, a3);
                *(float4*)(pp + 4) = make_float4(a4, a5, a6, a7);
                __syncthreads();
                float s = 0.f;
#pragma unroll
                for (int g = 0; g < 8; g++) s += sh.u.a.part[g][tid];
                g_ctx[b * 512 + tid] = s * inv;
            }
        } else if (t > 0 && bx < 144) {
            int u = bx - 64, tile = u >> 1, kh = u & 1;
            gemmT<2>(g_cdn, nullptr, nullptr,
                     g_emb_h, g_emb_l, 512, 1 << 30,
                     nullptr, nullptr, 0,
                     tile * 128, Vsz, kh * 256, kh * 256 + 256,
                     g_lgp[kh], 5120, nullptr, 0, sh);
        }
        gsync(gs);
    }

    // ---- epilogue ----
    {
        const float* h2last = g_h2[Tsz & 1];
        // E1: cdn-T(Tsz-1) (128-147) || logits-red(Tsz-2) (0-127)
        if (bx >= 128) {
            int u = bx - 128, ntile = u / 5, ks = u % 5;
            int kb, kl; cd_geom(ks, kb, kl);
            gemmT<2>(h2last, g_ctx, nullptr,
                     g_wcd_h, g_wcd_l, 1024, 1 << 30,
                     nullptr, nullptr, 0,
                     ntile * 128, 1 << 30, kb, kb + kl,
                     g_cdp + (long)ks * 32768, 512, nullptr, 0, sh);
        } else {
            int gid = bx * NTHR + tid;
            for (int e = gid; e < Bsz * Vsz; e += 128 * NTHR) {
                int m = e / Vsz, n = e - m * Vsz;
                out[((long)m * Tsz + (Tsz - 2)) * Vsz + n] =
                    g_lgp[0][m * 5120 + n] + g_lgp[1][m * 5120 + n] + bcls[n];
            }
        }
        gsync(gs);
        // E2: cdn-red(Tsz-1)
        {
            int gid = bx * NTHR + tid;
            if (gid < 32768) {
                float s = bcdn[gid & 511];
#pragma unroll
                for (int ks = 0; ks < 5; ks++) s += g_cdp[ks * 32768 + gid];
                g_cdn[gid] = fmaxf(s, 0.f);
            }
        }
        gsync(gs);
        // E3: logits-T(Tsz-1) on 80 blocks
        if (bx < 80) {
            int tile = bx >> 1, kh = bx & 1;
            gemmT<2>(g_cdn, nullptr, nullptr,
                     g_emb_h, g_emb_l, 512, 1 << 30,
                     nullptr, nullptr, 0,
                     tile * 128, Vsz, kh * 256, kh * 256 + 256,
                     g_lgp[kh], 5120, nullptr, 0, sh);
        }
        gsync(gs);
        // E4: logits-red(Tsz-1)
        {
            int gid = bx * NTHR + tid;
            for (int e = gid; e < Bsz * Vsz; e += GRID * NTHR) {
                int m = e / Vsz, n = e - m * Vsz;
                out[((long)m * Tsz + (Tsz - 1)) * Vsz + n] =
                    g_lgp[0][m * 5120 + n] + g_lgp[1][m * 5120 + n] + bcls[n];
            }
        }
    }
}

extern "C" void kernel_launch(void* const* d_in, const int* in_sizes, int n_in,
                              void* d_out, int out_size) {
    mega<<<GRID, NTHR>>>(
        (const float*)d_in[0],  (const int*)d_in[1],   (const float*)d_in[2],
        (const float*)d_in[3],  (const float*)d_in[4],
        (const float*)d_in[5],  (const float*)d_in[6],
        (const float*)d_in[7],  (const float*)d_in[8],
        (const float*)d_in[9],  (const float*)d_in[10],
        (const float*)d_in[11], (const float*)d_in[12],
        (const float*)d_in[13], (const float*)d_in[14],
        (const float*)d_in[15], (const float*)d_in[16],
        (const float*)d_in[17], (const float*)d_in[18],
        (const float*)d_in[19], (float*)d_out);
}